// round 9
// baseline (speedup 1.0000x reference)
#include <cuda_runtime.h>
#include <cstdint>

#define N_SRC   200000
#define D       128
#define N_RULES 250000
#define PERIOD  8

// One warp per rule. lane l owns columns [4l, 4l+4).
// Cache strategy (intrinsics ONLY — inline PTX breaks the remote toolchain):
//   - weights: __ldcv  (1.02GB pure stream; .cv does not allocate in L2, so it
//              cannot evict the gather table; LTS throughput is path-independent)
//   - output:  __stwt  (write-through, no write-allocate pollution)
//   - indices: __ldcs
//   - gather:  __ldg   (default; with streams not allocating, the 102MB table
//              stays resident in the 126MB L2)
__global__ __launch_bounds__(256, 8)
void weighted_rule_kernel(const float* __restrict__ layer_values,
                          const float* __restrict__ weights,
                          const int* __restrict__ indices,   // int32 (JAX x64 disabled)
                          float* __restrict__ out)
{
    const int warp_global = (blockIdx.x * blockDim.x + threadIdx.x) >> 5;
    if (warp_global >= N_RULES) return;
    const int lane = threadIdx.x & 31;

    const int*    ip   = indices + (size_t)warp_global * PERIOD;
    const float4* wrow = reinterpret_cast<const float4*>(
                             weights + (size_t)warp_global * PERIOD * D) + lane;

    // Prefetch all 8 indices up-front (uniform per warp).
    int src[PERIOD];
#pragma unroll
    for (int p = 0; p < PERIOD; ++p) src[p] = __ldcs(ip + p);

    float4 acc = make_float4(0.f, 0.f, 0.f, 0.f);

#pragma unroll
    for (int p = 0; p < PERIOD; ++p) {
        const float4 g = __ldg(reinterpret_cast<const float4*>(
                                   layer_values + (size_t)src[p] * D) + lane);
        const float4 w = __ldcv(wrow + p * (D / 4));
        acc.x = fmaf(g.x, w.x, acc.x);
        acc.y = fmaf(g.y, w.y, acc.y);
        acc.z = fmaf(g.z, w.z, acc.z);
        acc.w = fmaf(g.w, w.w, acc.w);
    }

    float4 r;
    r.x = tanhf(acc.x);
    r.y = tanhf(acc.y);
    r.z = tanhf(acc.z);
    r.w = tanhf(acc.w);

    __stwt(reinterpret_cast<float4*>(out + (size_t)warp_global * D) + lane, r);
}

extern "C" void kernel_launch(void* const* d_in, const int* in_sizes, int n_in,
                              void* d_out, int out_size)
{
    // Identify inputs by element count (robust to metadata ordering):
    const float* lv  = nullptr;
    const float* w   = nullptr;
    const int*   idx = nullptr;
    for (int i = 0; i < n_in; ++i) {
        const long long sz = in_sizes[i];
        if (sz == (long long)N_SRC * D)                 lv  = (const float*)d_in[i];
        else if (sz == (long long)N_RULES * PERIOD * D) w   = (const float*)d_in[i];
        else if (sz == (long long)N_RULES * PERIOD)     idx = (const int*)d_in[i];
    }

    float* out = (float*)d_out;  // [N_RULES, D] float32

    const int threads = 256;                 // 8 warps = 8 rules per block
    const int warps_per_block = threads / 32;
    const int blocks = (N_RULES + warps_per_block - 1) / warps_per_block;

    weighted_rule_kernel<<<blocks, threads>>>(lv, w, idx, out);
}

// round 10
// speedup vs baseline: 1.2000x; 1.2000x over previous
#include <cuda_runtime.h>
#include <cuda/annotated_ptr>
#include <cstdint>

#define N_SRC   200000
#define D       128
#define N_RULES 250000
#define PERIOD  8

// One warp per rule. lane l owns columns [4l, 4l+4).
// Cache strategy (no inline PTX — remote toolchain rejects it):
//   - gather:  annotated_ptr<persisting> -> L2 evict_last priority; pins the
//              102MB table in the 126MB L2 against the streaming traffic
//   - weights: __ldcs  (1.02GB pure stream, evict-first)    [R7, best known]
//   - output:  __stcs  (streaming store)                    [R7, best known]
//   - indices: __ldcs
__global__ __launch_bounds__(256, 8)
void weighted_rule_kernel(const float* __restrict__ layer_values,
                          const float* __restrict__ weights,
                          const int* __restrict__ indices,   // int32 (JAX x64 disabled)
                          float* __restrict__ out)
{
    const int warp_global = (blockIdx.x * blockDim.x + threadIdx.x) >> 5;
    if (warp_global >= N_RULES) return;
    const int lane = threadIdx.x & 31;

    cuda::annotated_ptr<const float4, cuda::access_property::persisting> gat(
        reinterpret_cast<const float4*>(layer_values));

    const int*    ip   = indices + (size_t)warp_global * PERIOD;
    const float4* wrow = reinterpret_cast<const float4*>(
                             weights + (size_t)warp_global * PERIOD * D) + lane;

    // Prefetch all 8 indices up-front (uniform per warp).
    int src[PERIOD];
#pragma unroll
    for (int p = 0; p < PERIOD; ++p) src[p] = __ldcs(ip + p);

    float4 acc = make_float4(0.f, 0.f, 0.f, 0.f);

#pragma unroll
    for (int p = 0; p < PERIOD; ++p) {
        const float4 g = gat[(size_t)src[p] * (D / 4) + lane];
        const float4 w = __ldcs(wrow + p * (D / 4));
        acc.x = fmaf(g.x, w.x, acc.x);
        acc.y = fmaf(g.y, w.y, acc.y);
        acc.z = fmaf(g.z, w.z, acc.z);
        acc.w = fmaf(g.w, w.w, acc.w);
    }

    float4 r;
    r.x = tanhf(acc.x);
    r.y = tanhf(acc.y);
    r.z = tanhf(acc.z);
    r.w = tanhf(acc.w);

    __stcs(reinterpret_cast<float4*>(out + (size_t)warp_global * D) + lane, r);
}

extern "C" void kernel_launch(void* const* d_in, const int* in_sizes, int n_in,
                              void* d_out, int out_size)
{
    // Identify inputs by element count (robust to metadata ordering):
    const float* lv  = nullptr;
    const float* w   = nullptr;
    const int*   idx = nullptr;
    for (int i = 0; i < n_in; ++i) {
        const long long sz = in_sizes[i];
        if (sz == (long long)N_SRC * D)                 lv  = (const float*)d_in[i];
        else if (sz == (long long)N_RULES * PERIOD * D) w   = (const float*)d_in[i];
        else if (sz == (long long)N_RULES * PERIOD)     idx = (const int*)d_in[i];
    }

    float* out = (float*)d_out;  // [N_RULES, D] float32

    const int threads = 256;                 // 8 warps = 8 rules per block
    const int warps_per_block = threads / 32;
    const int blocks = (N_RULES + warps_per_block - 1) / warps_per_block;

    weighted_rule_kernel<<<blocks, threads>>>(lv, w, idx, out);
}